// round 6
// baseline (speedup 1.0000x reference)
#include <cuda_runtime.h>

// ---------------------------------------------------------------------------
// FrontierLayerVN fused kernel, v6:
//   - 12 warps/SM persistent, R=8 rows per warp
//   - stage B sca part: duplicated (x,x) staging -> LDS.128 yields f32x2
//     operands directly, no splat MOVs (16-k chunks, 16 passes, prefetched)
//   - Wg1/Wv21/Wd1/Wv12 stored in interleaved-transposed layout:
//     one LDS.128 per lane per 4 output columns, conflict-free
//   - otherwise identical to v5
// ---------------------------------------------------------------------------

#define NWARPS 12
#define THREADS (NWARPS * 32)
#define FULLMASK 0xffffffffu

#define SZ_WV11 4096   // 64x64
#define SZ_WV21 2048   // 64x32 (interleaved-transposed)
#define SZ_WS1  40960  // 320x128
#define SZ_WG1  4096   // 128x32 (interleaved-transposed)
#define SZ_BG1  32
#define SZ_WD1  1024   // 32x32 (interleaved-transposed)
#define SZ_WV12 1024   // 32x32 (interleaved-transposed)
#define SZ_WS2  160
#define SZ_WEIGHTS (SZ_WV11 + SZ_WV21 + SZ_WS1 + SZ_WG1 + SZ_BG1 + SZ_WD1 + SZ_WV12 + SZ_WS2)
#define WS_FLOATS 384
#define SMEM_FLOATS (SZ_WEIGHTS + NWARPS * WS_FLOATS)   // 232192 B

typedef unsigned long long u64;

__device__ __forceinline__ u64 pk2(float x, float y) {
    u64 d; asm("mov.b64 %0, {%1, %2};" : "=l"(d) : "f"(x), "f"(y)); return d;
}
__device__ __forceinline__ void upk2(float& x, float& y, u64 d) {
    asm("mov.b64 {%0, %1}, %2;" : "=f"(x), "=f"(y) : "l"(d));
}
__device__ __forceinline__ void fma2(u64& a, u64 x, u64 w) {
    asm("fma.rn.f32x2 %0, %1, %2, %3;" : "=l"(a) : "l"(x), "l"(w), "l"(a));
}
__device__ __forceinline__ float fcomp(const float4& v, int e) {
    return (&v.x)[e];   // e compile-time under #pragma unroll
}

// stage-B inner loop over a staged 32-k chunk (layout [r][32] floats), splat form
__device__ __forceinline__ void b_chunk(
    u64* __restrict__ ps01, u64* __restrict__ ps23,
    const float4* __restrict__ wsv4, const float4* __restrict__ sWs1_f4,
    int k_base, int lane)
{
    for (int kq = 0; kq < 8; kq++) {
        float4 xs[8];
        #pragma unroll
        for (int r = 0; r < 8; r++) xs[r] = wsv4[r*8 + kq];
        #pragma unroll
        for (int e = 0; e < 4; e++) {
            int k = k_base + kq*4 + e;
            float4 w = sWs1_f4[k*32 + lane];
            u64 wa = pk2(w.x, w.y), wb = pk2(w.z, w.w);
            #pragma unroll
            for (int r = 0; r < 8; r++) {
                float x = fcomp(xs[r], e);
                u64 xx = pk2(x, x);
                fma2(ps01[r], xx, wa);
                fma2(ps23[r], xx, wb);
            }
        }
    }
}

// stage-B inner loop over a duplicated 16-k chunk (layout [r][16][2] floats)
__device__ __forceinline__ void b_chunk_dup(
    u64* __restrict__ ps01, u64* __restrict__ ps23,
    const ulonglong2* __restrict__ wsu2, const float4* __restrict__ sWs1_f4,
    int k_base, int lane)
{
    #pragma unroll
    for (int kq2 = 0; kq2 < 4; kq2++) {
        ulonglong2 xa[8], xb[8];
        #pragma unroll
        for (int r = 0; r < 8; r++) {
            xa[r] = wsu2[r*8 + kq2*2 + 0];   // (k0,k0),(k1,k1)
            xb[r] = wsu2[r*8 + kq2*2 + 1];   // (k2,k2),(k3,k3)
        }
        #pragma unroll
        for (int e = 0; e < 4; e++) {
            int k = k_base + kq2*4 + e;
            float4 w = sWs1_f4[k*32 + lane];
            u64 wa = pk2(w.x, w.y), wb = pk2(w.z, w.w);
            #pragma unroll
            for (int r = 0; r < 8; r++) {
                u64 xx = (e==0) ? xa[r].x : (e==1) ? xa[r].y
                       : (e==2) ? xb[r].x : xb[r].y;
                fma2(ps01[r], xx, wa);
                fma2(ps23[r], xx, wb);
            }
        }
    }
}

__global__ __launch_bounds__(THREADS, 1)
void frontier_vn_kernel(
    const float* __restrict__ g_sca,   // (N,256)
    const float* __restrict__ g_vec,   // (N,64,3)
    const int*   __restrict__ g_idx,   // (M,)
    const float* __restrict__ gWv11,   // (64,64)
    const float* __restrict__ gWv21,   // (64,32)
    const float* __restrict__ gWs1,    // (320,128)
    const float* __restrict__ gWg1,    // (128,32)
    const float* __restrict__ gbg1,    // (32,)
    const float* __restrict__ gWd1,    // (32,32)
    const float* __restrict__ gWv12,   // (32,32)
    const float* __restrict__ gWs2,    // (160,)
    float* __restrict__ out,           // (M,)
    int M)
{
    extern __shared__ float sm[];
    float* sWv11 = sm;
    float* sWv21 = sWv11 + SZ_WV11;   // interleaved-transposed
    float* sWs1  = sWv21 + SZ_WV21;
    float* sWg1  = sWs1  + SZ_WS1;    // interleaved-transposed
    float* sbg1  = sWg1  + SZ_WG1;
    float* sWd1  = sbg1  + SZ_BG1;    // interleaved-transposed
    float* sWv12 = sWd1  + SZ_WD1;    // interleaved-transposed
    float* sWs2  = sWv12 + SZ_WV12;
    float* scratch = sWs2 + SZ_WS2;

    const int tid = threadIdx.x;

    // ---- cooperative weight staging ----
    {
        const float4* s; float4* d;
        d = (float4*)sWv11; s = (const float4*)gWv11;
        for (int i = tid; i < SZ_WV11/4; i += THREADS) d[i] = s[i];
        d = (float4*)sWs1;  s = (const float4*)gWs1;
        for (int i = tid; i < SZ_WS1/4;  i += THREADS) d[i] = s[i];
        d = (float4*)sbg1;  s = (const float4*)gbg1;
        for (int i = tid; i < SZ_BG1/4;  i += THREADS) d[i] = s[i];
        d = (float4*)sWs2;  s = (const float4*)gWs2;
        for (int i = tid; i < SZ_WS2/4;  i += THREADS) d[i] = s[i];
        // interleaved-transposed: element (k,o) of (K,32) goes to
        //   f4-group (k>>2), lane o, slot (k&3)  ->  float idx (k>>2)*128 + o*4 + (k&3)
        for (int i = tid; i < SZ_WG1; i += THREADS) {
            int k = i >> 5, o = i & 31;
            sWg1[(k >> 2)*128 + (o << 2) + (k & 3)] = gWg1[i];
        }
        for (int i = tid; i < SZ_WV21; i += THREADS) {
            int k = i >> 5, o = i & 31;
            sWv21[(k >> 2)*128 + (o << 2) + (k & 3)] = gWv21[i];
        }
        for (int i = tid; i < SZ_WD1; i += THREADS) {
            int k = i >> 5, o = i & 31;
            sWd1[(k >> 2)*128 + (o << 2) + (k & 3)] = gWd1[i];
        }
        for (int i = tid; i < SZ_WV12; i += THREADS) {
            int k = i >> 5, o = i & 31;
            sWv12[(k >> 2)*128 + (o << 2) + (k & 3)] = gWv12[i];
        }
    }
    __syncthreads();

    const int warp = tid >> 5;
    const int lane = tid & 31;
    float* ws = scratch + warp * WS_FLOATS;
    float4* wsv4 = (float4*)ws;

    const float2* sWv11_f2 = (const float2*)sWv11;
    const float4* sWs1_f4  = (const float4*)sWs1;
    const float4* sWg1_f4  = (const float4*)sWg1;
    const float4* sWv21_f4 = (const float4*)sWv21;
    const float4* sWd1_f4  = (const float4*)sWd1;
    const float4* sWv12_f4 = (const float4*)sWv12;
    const float4* sWs2_f4  = (const float4*)sWs2;
    const float4* g_sca4   = (const float4*)g_sca;
    const float4* g_vec4   = (const float4*)g_vec;

    const int r_ln = lane >> 2;      // row handled by this lane in gathers
    const int q_ln = lane & 3;

    for (int base = (blockIdx.x * NWARPS + warp) * 8; base < M;
         base += gridDim.x * NWARPS * 8)
    {
        int m_dyn = base + r_ln;
        const int idx_dyn = g_idx[(m_dyn < M) ? m_dyn : (M - 1)];
        const size_t vbase = (size_t)idx_dyn * 48;   // f4 units
        const size_t sbase = (size_t)idx_dyn * 64;   // f4 units

        // =================== Stage A: vec -> vh (single pass, R=8) ==========
        u64 pax[8], pay[8], paz[8];
        #pragma unroll
        for (int r = 0; r < 8; r++) { pax[r]=0ull; pay[r]=0ull; paz[r]=0ull; }

        float4 vf0 = g_vec4[vbase + 3*q_ln + 0];
        float4 vf1 = g_vec4[vbase + 3*q_ln + 1];
        float4 vf2 = g_vec4[vbase + 3*q_ln + 2];

        for (int chunk = 0; chunk < 4; chunk++) {
            __syncwarp();
            wsv4[r_ln*12 + 3*q_ln + 0] = vf0;
            wsv4[r_ln*12 + 3*q_ln + 1] = vf1;
            wsv4[r_ln*12 + 3*q_ln + 2] = vf2;
            if (chunk < 3) {
                vf0 = g_vec4[vbase + (chunk+1)*12 + 3*q_ln + 0];
                vf1 = g_vec4[vbase + (chunk+1)*12 + 3*q_ln + 1];
                vf2 = g_vec4[vbase + (chunk+1)*12 + 3*q_ln + 2];
            }
            __syncwarp();
            for (int cq = 0; cq < 4; cq++) {
                u64 ww[4];
                #pragma unroll
                for (int e = 0; e < 4; e++) {
                    float2 w2 = sWv11_f2[(chunk*16 + cq*4 + e)*32 + lane];
                    ww[e] = pk2(w2.x, w2.y);
                }
                #pragma unroll
                for (int r = 0; r < 8; r++) {
                    float4 f0 = wsv4[r*12 + 3*cq + 0];
                    float4 f1 = wsv4[r*12 + 3*cq + 1];
                    float4 f2 = wsv4[r*12 + 3*cq + 2];
                    float vcx[4] = {f0.x, f0.w, f1.z, f2.y};
                    float vcy[4] = {f0.y, f1.x, f1.w, f2.z};
                    float vcz[4] = {f0.z, f1.y, f2.x, f2.w};
                    #pragma unroll
                    for (int e = 0; e < 4; e++) {
                        fma2(pax[r], pk2(vcx[e], vcx[e]), ww[e]);
                        fma2(pay[r], pk2(vcy[e], vcy[e]), ww[e]);
                        fma2(paz[r], pk2(vcz[e], vcz[e]), ww[e]);
                    }
                }
            }
        }

        // =================== Stage B: s1 ====================================
        u64 ps01[8], ps23[8];
        #pragma unroll
        for (int r = 0; r < 8; r++) { ps01[r]=0ull; ps23[r]=0ull; }

        // prefetch first sca chunk (16 k per pass, 4 floats per lane)
        float4 sf = g_sca4[sbase + q_ln];

        // vn passes: k in [0,64), two 32-k chunks; norms computed inline
        #pragma unroll
        for (int chunk = 0; chunk < 2; chunk++) {
            __syncwarp();
            if ((lane >> 4) == chunk) {
                int klocal = 2*lane - 32*chunk;   // even, 0..30
                #pragma unroll
                for (int r = 0; r < 8; r++) {
                    float x0,x1,y0,y1,z0,z1;
                    upk2(x0,x1,pax[r]); upk2(y0,y1,pay[r]); upk2(z0,z1,paz[r]);
                    float2 nn;
                    nn.x = sqrtf(x0*x0 + y0*y0 + z0*z0);
                    nn.y = sqrtf(x1*x1 + y1*y1 + z1*z1);
                    *(float2*)(ws + r*32 + klocal) = nn;
                }
            }
            __syncwarp();
            b_chunk(ps01, ps23, wsv4, sWs1_f4, chunk*32, lane);
        }

        // sca passes: k in [64,320), sixteen 16-k duplicated chunks, prefetched
        for (int pass = 0; pass < 16; pass++) {
            __syncwarp();
            wsv4[r_ln*8 + q_ln*2 + 0] = make_float4(sf.x, sf.x, sf.y, sf.y);
            wsv4[r_ln*8 + q_ln*2 + 1] = make_float4(sf.z, sf.z, sf.w, sf.w);
            if (pass < 15) sf = g_sca4[sbase + (pass+1)*4 + q_ln];
            __syncwarp();
            b_chunk_dup(ps01, ps23, (const ulonglong2*)ws, sWs1_f4,
                        64 + pass*16, lane);
        }

        // =================== Stage C: gate (2x 4-row passes, j-halves) ======
        float gg[8];
        #pragma unroll
        for (int p = 0; p < 2; p++) {
            u64 g01 = 0ull, g23 = 0ull;
            #pragma unroll
            for (int half = 0; half < 2; half++) {
                __syncwarp();
                if ((lane >> 4) == half) {
                    int jl = lane & 15;
                    #pragma unroll
                    for (int r2 = 0; r2 < 4; r2++) {
                        float4 sv;
                        upk2(sv.x, sv.y, ps01[p*4+r2]);
                        upk2(sv.z, sv.w, ps23[p*4+r2]);
                        wsv4[r2*16 + jl] = sv;
                    }
                }
                __syncwarp();
                for (int jq = 0; jq < 16; jq++) {
                    float4 x0 = wsv4[0*16 + jq];
                    float4 x1 = wsv4[1*16 + jq];
                    float4 x2 = wsv4[2*16 + jq];
                    float4 x3 = wsv4[3*16 + jq];
                    float4 w4 = sWg1_f4[(half*16 + jq)*32 + lane];
                    #pragma unroll
                    for (int e = 0; e < 4; e++) {
                        float w = fcomp(w4, e);
                        u64 ww = pk2(w, w);
                        fma2(g01, pk2(fcomp(x0,e), fcomp(x1,e)), ww);
                        fma2(g23, pk2(fcomp(x2,e), fcomp(x3,e)), ww);
                    }
                }
            }
            float a,b,c,d;
            upk2(a,b,g01); upk2(c,d,g23);
            float bias = sbg1[lane];
            gg[p*4+0] = 1.f / (1.f + __expf(-(a + bias)));
            gg[p*4+1] = 1.f / (1.f + __expf(-(b + bias)));
            gg[p*4+2] = 1.f / (1.f + __expf(-(c + bias)));
            gg[p*4+3] = 1.f / (1.f + __expf(-(d + bias)));
        }

        // retire ps: fold leaky(s1) . Ws2_tail into per-lane partials
        float partB[8];
        {
            float4 w2tail = sWs2_f4[8 + lane];
            #pragma unroll
            for (int r = 0; r < 8; r++) {
                float s0,s1v,s2,s3;
                upk2(s0,s1v,ps01[r]); upk2(s2,s3,ps23[r]);
                float p = ((s0  >= 0.f) ? s0  : 0.01f*s0)  * w2tail.x;
                p      += ((s1v >= 0.f) ? s1v : 0.01f*s1v) * w2tail.y;
                p      += ((s2  >= 0.f) ? s2  : 0.01f*s2)  * w2tail.z;
                p      += ((s3  >= 0.f) ? s3  : 0.01f*s3)  * w2tail.w;
                partB[r] = p;
            }
        }

        // =================== Stages D/E/F fused per 4-row half ==============
        float w2head = sWs2[lane];
        #pragma unroll
        for (int p = 0; p < 2; p++) {
            // ---- D: out_vec ----
            u64 oxy[4] = {0ull,0ull,0ull,0ull};
            float ozv[4] = {0.f,0.f,0.f,0.f};
            #pragma unroll
            for (int t = 0; t < 2; t++) {
                __syncwarp();
                if ((lane >> 4) == t) {
                    int h0 = 2*lane - 32*t;
                    #pragma unroll
                    for (int r2 = 0; r2 < 4; r2++) {
                        *(u64*)(ws + r2*96 +  0 + h0) = pax[p*4+r2];
                        *(u64*)(ws + r2*96 + 32 + h0) = pay[p*4+r2];
                        *(u64*)(ws + r2*96 + 64 + h0) = paz[p*4+r2];
                    }
                }
                __syncwarp();
                for (int hq = 0; hq < 8; hq++) {
                    float4 xv[4][3];
                    #pragma unroll
                    for (int r2 = 0; r2 < 4; r2++) {
                        xv[r2][0] = wsv4[r2*24 + 0*8 + hq];
                        xv[r2][1] = wsv4[r2*24 + 1*8 + hq];
                        xv[r2][2] = wsv4[r2*24 + 2*8 + hq];
                    }
                    float4 w4 = sWv21_f4[(t*8 + hq)*32 + lane];
                    #pragma unroll
                    for (int e = 0; e < 4; e++) {
                        float w = fcomp(w4, e);
                        u64 ww = pk2(w, w);
                        #pragma unroll
                        for (int r2 = 0; r2 < 4; r2++) {
                            fma2(oxy[r2], pk2(fcomp(xv[r2][0],e), fcomp(xv[r2][1],e)), ww);
                            ozv[r2] += w * fcomp(xv[r2][2], e);
                        }
                    }
                }
            }
            float v2x[4], v2y[4], v2z[4];
            #pragma unroll
            for (int r2 = 0; r2 < 4; r2++) {
                float ox, oy; upk2(ox, oy, oxy[r2]);
                float g = gg[p*4+r2];
                v2x[r2] = g*ox; v2y[r2] = g*oy; v2z[r2] = g*ozv[r2];
            }

            // ---- E: VNLeakyReLU ----
            __syncwarp();
            #pragma unroll
            for (int r2 = 0; r2 < 4; r2++) {
                ws[r2*96 +  0 + lane] = v2x[r2];
                ws[r2*96 + 32 + lane] = v2y[r2];
                ws[r2*96 + 64 + lane] = v2z[r2];
            }
            __syncwarp();
            u64 dxy[4] = {0ull,0ull,0ull,0ull};
            float dzv[4] = {0.f,0.f,0.f,0.f};
            for (int cq = 0; cq < 8; cq++) {
                float4 xv[4][3];
                #pragma unroll
                for (int r2 = 0; r2 < 4; r2++) {
                    xv[r2][0] = wsv4[r2*24 + 0*8 + cq];
                    xv[r2][1] = wsv4[r2*24 + 1*8 + cq];
                    xv[r2][2] = wsv4[r2*24 + 2*8 + cq];
                }
                float4 w4 = sWd1_f4[cq*32 + lane];
                #pragma unroll
                for (int e = 0; e < 4; e++) {
                    float w = fcomp(w4, e);
                    u64 ww = pk2(w, w);
                    #pragma unroll
                    for (int r2 = 0; r2 < 4; r2++) {
                        fma2(dxy[r2], pk2(fcomp(xv[r2][0],e), fcomp(xv[r2][1],e)), ww);
                        dzv[r2] += w * fcomp(xv[r2][2], e);
                    }
                }
            }
            float v3x[4], v3y[4], v3z[4];
            #pragma unroll
            for (int r2 = 0; r2 < 4; r2++) {
                float dx, dy; upk2(dx, dy, dxy[r2]);
                float dz = dzv[r2];
                float dot = v2x[r2]*dx + v2y[r2]*dy + v2z[r2]*dz;
                float dsq = dx*dx + dy*dy + dz*dz;
                float tt  = dot / (dsq + 1e-6f);
                float rx = (dot >= 0.f) ? v2x[r2] : (v2x[r2] - tt*dx);
                float ry = (dot >= 0.f) ? v2y[r2] : (v2y[r2] - tt*dy);
                float rz = (dot >= 0.f) ? v2z[r2] : (v2z[r2] - tt*dz);
                v3x[r2] = 0.2f*v2x[r2] + 0.8f*rx;
                v3y[r2] = 0.2f*v2y[r2] + 0.8f*ry;
                v3z[r2] = 0.2f*v2z[r2] + 0.8f*rz;
            }

            // ---- F: layer 2 + output ----
            __syncwarp();
            #pragma unroll
            for (int r2 = 0; r2 < 4; r2++) {
                ws[r2*96 +  0 + lane] = v3x[r2];
                ws[r2*96 + 32 + lane] = v3y[r2];
                ws[r2*96 + 64 + lane] = v3z[r2];
            }
            __syncwarp();
            u64 bxy[4] = {0ull,0ull,0ull,0ull};
            float bzv[4] = {0.f,0.f,0.f,0.f};
            for (int cq = 0; cq < 8; cq++) {
                float4 xv[4][3];
                #pragma unroll
                for (int r2 = 0; r2 < 4; r2++) {
                    xv[r2][0] = wsv4[r2*24 + 0*8 + cq];
                    xv[r2][1] = wsv4[r2*24 + 1*8 + cq];
                    xv[r2][2] = wsv4[r2*24 + 2*8 + cq];
                }
                float4 w4 = sWv12_f4[cq*32 + lane];
                #pragma unroll
                for (int e = 0; e < 4; e++) {
                    float w = fcomp(w4, e);
                    u64 ww = pk2(w, w);
                    #pragma unroll
                    for (int r2 = 0; r2 < 4; r2++) {
                        fma2(bxy[r2], pk2(fcomp(xv[r2][0],e), fcomp(xv[r2][1],e)), ww);
                        bzv[r2] += w * fcomp(xv[r2][2], e);
                    }
                }
            }
            float res[4];
            #pragma unroll
            for (int r2 = 0; r2 < 4; r2++) {
                float bx, by; upk2(bx, by, bxy[r2]);
                float bz = bzv[r2];
                float vn2 = sqrtf(bx*bx + by*by + bz*bz);
                float pp = vn2 * w2head + partB[p*4+r2];
                #pragma unroll
                for (int off = 16; off > 0; off >>= 1)
                    pp += __shfl_xor_sync(FULLMASK, pp, off);
                res[r2] = pp;
            }
            if (lane == 0) {
                int mb = base + p*4;
                if (mb + 3 < M) {
                    *(float4*)(out + mb) = make_float4(res[0], res[1], res[2], res[3]);
                } else {
                    #pragma unroll
                    for (int r2 = 0; r2 < 4; r2++)
                        if (mb + r2 < M) out[mb + r2] = res[r2];
                }
            }
        }
        __syncwarp();
    }
}

extern "C" void kernel_launch(void* const* d_in, const int* in_sizes, int n_in,
                              void* d_out, int out_size)
{
    const float* g_sca  = (const float*)d_in[0];
    const float* g_vec  = (const float*)d_in[1];
    const int*   g_idx  = (const int*)  d_in[2];
    const float* gWv11  = (const float*)d_in[3];
    const float* gWv21  = (const float*)d_in[4];
    const float* gWs1   = (const float*)d_in[5];
    const float* gWg1   = (const float*)d_in[6];
    const float* gbg1   = (const float*)d_in[7];
    const float* gWd1   = (const float*)d_in[8];
    const float* gWv12  = (const float*)d_in[9];
    const float* gWs2   = (const float*)d_in[11];
    float* out = (float*)d_out;
    const int M = in_sizes[2];

    const int smem_bytes = SMEM_FLOATS * (int)sizeof(float);  // 232192 B
    cudaFuncSetAttribute(frontier_vn_kernel,
                         cudaFuncAttributeMaxDynamicSharedMemorySize, smem_bytes);

    int sms = 148;
    cudaDeviceGetAttribute(&sms, cudaDevAttrMultiProcessorCount, 0);

    frontier_vn_kernel<<<sms, THREADS, smem_bytes>>>(
        g_sca, g_vec, g_idx,
        gWv11, gWv21, gWs1, gWg1, gbg1, gWd1, gWv12, gWs2,
        out, M);
}

// round 7
// speedup vs baseline: 1.0720x; 1.0720x over previous
#include <cuda_runtime.h>

// ---------------------------------------------------------------------------
// FrontierLayerVN fused kernel, v7:
//   - base = v5 (679us): 12 warps/SM persistent, R=8 rows/warp
//   - stage B rewritten as ROW-PAIR f32x2: accumulate (s1_r0[j], s1_r1[j]);
//     activations staged [k][r] so LDS.128 yields row-pair u64 operands with
//     zero packing; only weights splatted (4/k shared across 8 rows,
//     vs 8 x-splats/k in v5)
//   - vn values staged as row-pair u64s directly
//   - Wg1/Wv21/Wd1/Wv12 in interleaved-transposed layout (LDS.128 per 4 cols)
// ---------------------------------------------------------------------------

#define NWARPS 12
#define THREADS (NWARPS * 32)
#define FULLMASK 0xffffffffu

#define SZ_WV11 4096   // 64x64
#define SZ_WV21 2048   // 64x32 (interleaved-transposed)
#define SZ_WS1  40960  // 320x128
#define SZ_WG1  4096   // 128x32 (interleaved-transposed)
#define SZ_BG1  32
#define SZ_WD1  1024   // 32x32 (interleaved-transposed)
#define SZ_WV12 1024   // 32x32 (interleaved-transposed)
#define SZ_WS2  160
#define SZ_WEIGHTS (SZ_WV11 + SZ_WV21 + SZ_WS1 + SZ_WG1 + SZ_BG1 + SZ_WD1 + SZ_WV12 + SZ_WS2)
#define WS_FLOATS 384
#define SMEM_FLOATS (SZ_WEIGHTS + NWARPS * WS_FLOATS)   // 232192 B

typedef unsigned long long u64;

__device__ __forceinline__ u64 pk2(float x, float y) {
    u64 d; asm("mov.b64 %0, {%1, %2};" : "=l"(d) : "f"(x), "f"(y)); return d;
}
__device__ __forceinline__ void upk2(float& x, float& y, u64 d) {
    asm("mov.b64 {%0, %1}, %2;" : "=f"(x), "=f"(y) : "l"(d));
}
__device__ __forceinline__ void fma2(u64& a, u64 x, u64 w) {
    asm("fma.rn.f32x2 %0, %1, %2, %3;" : "=l"(a) : "l"(x), "l"(w), "l"(a));
}
__device__ __forceinline__ float fcomp(const float4& v, int e) {
    return (&v.x)[e];   // e compile-time under #pragma unroll
}

// stage-B row-pair inner loop over a staged 32-k chunk, layout x[k][r] (8 r).
// ps[jj*4 + p] accumulates (s1_{2p}[4l+jj], s1_{2p+1}[4l+jj]).
__device__ __forceinline__ void b_chunk_rp(
    u64* __restrict__ ps,
    const float* __restrict__ ws, const float4* __restrict__ sWs1_f4,
    int k_base, int lane)
{
    const ulonglong2* wsu2 = (const ulonglong2*)ws;
    #pragma unroll 4
    for (int k = 0; k < 32; k++) {
        float4 w = sWs1_f4[(k_base + k)*32 + lane];
        u64 w0 = pk2(w.x, w.x);
        u64 w1 = pk2(w.y, w.y);
        u64 w2 = pk2(w.z, w.z);
        u64 w3 = pk2(w.w, w.w);
        ulonglong2 xa = wsu2[k*2 + 0];   // pairs (r0,r1),(r2,r3)
        ulonglong2 xb = wsu2[k*2 + 1];   // pairs (r4,r5),(r6,r7)
        fma2(ps[ 0], xa.x, w0); fma2(ps[ 1], xa.y, w0);
        fma2(ps[ 2], xb.x, w0); fma2(ps[ 3], xb.y, w0);
        fma2(ps[ 4], xa.x, w1); fma2(ps[ 5], xa.y, w1);
        fma2(ps[ 6], xb.x, w1); fma2(ps[ 7], xb.y, w1);
        fma2(ps[ 8], xa.x, w2); fma2(ps[ 9], xa.y, w2);
        fma2(ps[10], xb.x, w2); fma2(ps[11], xb.y, w2);
        fma2(ps[12], xa.x, w3); fma2(ps[13], xa.y, w3);
        fma2(ps[14], xb.x, w3); fma2(ps[15], xb.y, w3);
    }
}

__global__ __launch_bounds__(THREADS, 1)
void frontier_vn_kernel(
    const float* __restrict__ g_sca,   // (N,256)
    const float* __restrict__ g_vec,   // (N,64,3)
    const int*   __restrict__ g_idx,   // (M,)
    const float* __restrict__ gWv11,   // (64,64)
    const float* __restrict__ gWv21,   // (64,32)
    const float* __restrict__ gWs1,    // (320,128)
    const float* __restrict__ gWg1,    // (128,32)
    const float* __restrict__ gbg1,    // (32,)
    const float* __restrict__ gWd1,    // (32,32)
    const float* __restrict__ gWv12,   // (32,32)
    const float* __restrict__ gWs2,    // (160,)
    float* __restrict__ out,           // (M,)
    int M)
{
    extern __shared__ float sm[];
    float* sWv11 = sm;
    float* sWv21 = sWv11 + SZ_WV11;   // interleaved-transposed
    float* sWs1  = sWv21 + SZ_WV21;
    float* sWg1  = sWs1  + SZ_WS1;    // interleaved-transposed
    float* sbg1  = sWg1  + SZ_WG1;
    float* sWd1  = sbg1  + SZ_BG1;    // interleaved-transposed
    float* sWv12 = sWd1  + SZ_WD1;    // interleaved-transposed
    float* sWs2  = sWv12 + SZ_WV12;
    float* scratch = sWs2 + SZ_WS2;

    const int tid = threadIdx.x;

    // ---- cooperative weight staging ----
    {
        const float4* s; float4* d;
        d = (float4*)sWv11; s = (const float4*)gWv11;
        for (int i = tid; i < SZ_WV11/4; i += THREADS) d[i] = s[i];
        d = (float4*)sWs1;  s = (const float4*)gWs1;
        for (int i = tid; i < SZ_WS1/4;  i += THREADS) d[i] = s[i];
        d = (float4*)sbg1;  s = (const float4*)gbg1;
        for (int i = tid; i < SZ_BG1/4;  i += THREADS) d[i] = s[i];
        d = (float4*)sWs2;  s = (const float4*)gWs2;
        for (int i = tid; i < SZ_WS2/4;  i += THREADS) d[i] = s[i];
        // interleaved-transposed: (k,o) of (K,32) -> float idx (k>>2)*128 + o*4 + (k&3)
        for (int i = tid; i < SZ_WG1; i += THREADS) {
            int k = i >> 5, o = i & 31;
            sWg1[(k >> 2)*128 + (o << 2) + (k & 3)] = gWg1[i];
        }
        for (int i = tid; i < SZ_WV21; i += THREADS) {
            int k = i >> 5, o = i & 31;
            sWv21[(k >> 2)*128 + (o << 2) + (k & 3)] = gWv21[i];
        }
        for (int i = tid; i < SZ_WD1; i += THREADS) {
            int k = i >> 5, o = i & 31;
            sWd1[(k >> 2)*128 + (o << 2) + (k & 3)] = gWd1[i];
        }
        for (int i = tid; i < SZ_WV12; i += THREADS) {
            int k = i >> 5, o = i & 31;
            sWv12[(k >> 2)*128 + (o << 2) + (k & 3)] = gWv12[i];
        }
    }
    __syncthreads();

    const int warp = tid >> 5;
    const int lane = tid & 31;
    float* ws = scratch + warp * WS_FLOATS;
    float4* wsv4 = (float4*)ws;

    const float2* sWv11_f2 = (const float2*)sWv11;
    const float4* sWs1_f4  = (const float4*)sWs1;
    const float4* sWg1_f4  = (const float4*)sWg1;
    const float4* sWv21_f4 = (const float4*)sWv21;
    const float4* sWd1_f4  = (const float4*)sWd1;
    const float4* sWv12_f4 = (const float4*)sWv12;
    const float4* sWs2_f4  = (const float4*)sWs2;
    const float4* g_sca4   = (const float4*)g_sca;
    const float4* g_vec4   = (const float4*)g_vec;

    const int r_ln = lane >> 2;      // row handled by this lane in gathers
    const int q_ln = lane & 3;

    for (int base = (blockIdx.x * NWARPS + warp) * 8; base < M;
         base += gridDim.x * NWARPS * 8)
    {
        int m_dyn = base + r_ln;
        const int idx_dyn = g_idx[(m_dyn < M) ? m_dyn : (M - 1)];
        const size_t vbase = (size_t)idx_dyn * 48;   // f4 units
        const size_t sbase = (size_t)idx_dyn * 64;   // f4 units

        // =================== Stage A: vec -> vh (single pass, R=8) ==========
        u64 pax[8], pay[8], paz[8];
        #pragma unroll
        for (int r = 0; r < 8; r++) { pax[r]=0ull; pay[r]=0ull; paz[r]=0ull; }

        float4 vf0 = g_vec4[vbase + 3*q_ln + 0];
        float4 vf1 = g_vec4[vbase + 3*q_ln + 1];
        float4 vf2 = g_vec4[vbase + 3*q_ln + 2];

        for (int chunk = 0; chunk < 4; chunk++) {
            __syncwarp();
            wsv4[r_ln*12 + 3*q_ln + 0] = vf0;
            wsv4[r_ln*12 + 3*q_ln + 1] = vf1;
            wsv4[r_ln*12 + 3*q_ln + 2] = vf2;
            if (chunk < 3) {
                vf0 = g_vec4[vbase + (chunk+1)*12 + 3*q_ln + 0];
                vf1 = g_vec4[vbase + (chunk+1)*12 + 3*q_ln + 1];
                vf2 = g_vec4[vbase + (chunk+1)*12 + 3*q_ln + 2];
            }
            __syncwarp();
            for (int cq = 0; cq < 4; cq++) {
                u64 ww[4];
                #pragma unroll
                for (int e = 0; e < 4; e++) {
                    float2 w2 = sWv11_f2[(chunk*16 + cq*4 + e)*32 + lane];
                    ww[e] = pk2(w2.x, w2.y);
                }
                #pragma unroll
                for (int r = 0; r < 8; r++) {
                    float4 f0 = wsv4[r*12 + 3*cq + 0];
                    float4 f1 = wsv4[r*12 + 3*cq + 1];
                    float4 f2 = wsv4[r*12 + 3*cq + 2];
                    float vcx[4] = {f0.x, f0.w, f1.z, f2.y};
                    float vcy[4] = {f0.y, f1.x, f1.w, f2.z};
                    float vcz[4] = {f0.z, f1.y, f2.x, f2.w};
                    #pragma unroll
                    for (int e = 0; e < 4; e++) {
                        fma2(pax[r], pk2(vcx[e], vcx[e]), ww[e]);
                        fma2(pay[r], pk2(vcy[e], vcy[e]), ww[e]);
                        fma2(paz[r], pk2(vcz[e], vcz[e]), ww[e]);
                    }
                }
            }
        }

        // =================== Stage B: s1 (row-pair form) ====================
        u64 ps[16];
        #pragma unroll
        for (int i = 0; i < 16; i++) ps[i] = 0ull;

        // prefetch first sca chunk (32 k per pass; lane holds 8 k of row r_ln)
        float4 sf0 = g_sca4[sbase + q_ln];
        float4 sf1 = g_sca4[sbase + q_ln + 4];

        // vn chunks: k=h in [0,64), two 32-k chunks; layout [k][r] pairs
        #pragma unroll
        for (int chunk = 0; chunk < 2; chunk++) {
            __syncwarp();
            if ((lane >> 4) == chunk) {
                int klocal = 2*lane - 32*chunk;   // even, 0..30
                #pragma unroll
                for (int p = 0; p < 4; p++) {
                    float x0l,x0h,y0l,y0h,z0l,z0h;   // row 2p
                    float x1l,x1h,y1l,y1h,z1l,z1h;   // row 2p+1
                    upk2(x0l,x0h, pax[2*p]);   upk2(y0l,y0h, pay[2*p]);   upk2(z0l,z0h, paz[2*p]);
                    upk2(x1l,x1h, pax[2*p+1]); upk2(y1l,y1h, pay[2*p+1]); upk2(z1l,z1h, paz[2*p+1]);
                    float n0a = sqrtf(x0l*x0l + y0l*y0l + z0l*z0l);  // h0, row 2p
                    float n0b = sqrtf(x1l*x1l + y1l*y1l + z1l*z1l);  // h0, row 2p+1
                    float n1a = sqrtf(x0h*x0h + y0h*y0h + z0h*z0h);  // h1, row 2p
                    float n1b = sqrtf(x1h*x1h + y1h*y1h + z1h*z1h);  // h1, row 2p+1
                    *(u64*)(ws + klocal*8 + 2*p)       = pk2(n0a, n0b);
                    *(u64*)(ws + (klocal+1)*8 + 2*p)   = pk2(n1a, n1b);
                }
            }
            __syncwarp();
            b_chunk_rp(ps, ws, sWs1_f4, chunk*32, lane);
        }

        // sca passes: k in [64,320), eight 32-k chunks, layout [k][r], prefetch
        for (int pass = 0; pass < 8; pass++) {
            __syncwarp();
            ws[(q_ln*4 + 0)*8 + r_ln] = sf0.x;
            ws[(q_ln*4 + 1)*8 + r_ln] = sf0.y;
            ws[(q_ln*4 + 2)*8 + r_ln] = sf0.z;
            ws[(q_ln*4 + 3)*8 + r_ln] = sf0.w;
            ws[(16 + q_ln*4 + 0)*8 + r_ln] = sf1.x;
            ws[(16 + q_ln*4 + 1)*8 + r_ln] = sf1.y;
            ws[(16 + q_ln*4 + 2)*8 + r_ln] = sf1.z;
            ws[(16 + q_ln*4 + 3)*8 + r_ln] = sf1.w;
            if (pass < 7) {
                sf0 = g_sca4[sbase + (pass+1)*8 + q_ln];
                sf1 = g_sca4[sbase + (pass+1)*8 + q_ln + 4];
            }
            __syncwarp();
            b_chunk_rp(ps, ws, sWs1_f4, 64 + pass*32, lane);
        }

        // =================== Stage C: gate (2x 4-row passes, j-halves) ======
        float gg[8];
        #pragma unroll
        for (int p = 0; p < 2; p++) {
            u64 g01 = 0ull, g23 = 0ull;
            #pragma unroll
            for (int half = 0; half < 2; half++) {
                __syncwarp();
                if ((lane >> 4) == half) {
                    int jl = lane & 15;
                    #pragma unroll
                    for (int r2 = 0; r2 < 4; r2++) {
                        int pr = p*2 + (r2 >> 1);
                        float a0,a1,b0,b1,c0,c1,d0,d1;
                        upk2(a0,a1, ps[ 0 + pr]);
                        upk2(b0,b1, ps[ 4 + pr]);
                        upk2(c0,c1, ps[ 8 + pr]);
                        upk2(d0,d1, ps[12 + pr]);
                        float4 sv = (r2 & 1) ? make_float4(a1,b1,c1,d1)
                                             : make_float4(a0,b0,c0,d0);
                        wsv4[r2*16 + jl] = sv;
                    }
                }
                __syncwarp();
                for (int jq = 0; jq < 16; jq++) {
                    float4 x0 = wsv4[0*16 + jq];
                    float4 x1 = wsv4[1*16 + jq];
                    float4 x2 = wsv4[2*16 + jq];
                    float4 x3 = wsv4[3*16 + jq];
                    float4 w4 = sWg1_f4[(half*16 + jq)*32 + lane];
                    #pragma unroll
                    for (int e = 0; e < 4; e++) {
                        float w = fcomp(w4, e);
                        u64 ww = pk2(w, w);
                        fma2(g01, pk2(fcomp(x0,e), fcomp(x1,e)), ww);
                        fma2(g23, pk2(fcomp(x2,e), fcomp(x3,e)), ww);
                    }
                }
            }
            float a,b,c,d;
            upk2(a,b,g01); upk2(c,d,g23);
            float bias = sbg1[lane];
            gg[p*4+0] = 1.f / (1.f + __expf(-(a + bias)));
            gg[p*4+1] = 1.f / (1.f + __expf(-(b + bias)));
            gg[p*4+2] = 1.f / (1.f + __expf(-(c + bias)));
            gg[p*4+3] = 1.f / (1.f + __expf(-(d + bias)));
        }

        // retire ps: fold leaky(s1) . Ws2_tail into per-lane partials
        float partB[8];
        {
            float4 w2tail = sWs2_f4[8 + lane];
            #pragma unroll
            for (int r = 0; r < 8; r++) {
                int pr = r >> 1;
                float a0,a1,b0,b1,c0,c1,d0,d1;
                upk2(a0,a1, ps[ 0 + pr]);
                upk2(b0,b1, ps[ 4 + pr]);
                upk2(c0,c1, ps[ 8 + pr]);
                upk2(d0,d1, ps[12 + pr]);
                float s0  = (r & 1) ? a1 : a0;
                float s1v = (r & 1) ? b1 : b0;
                float s2  = (r & 1) ? c1 : c0;
                float s3  = (r & 1) ? d1 : d0;
                float p = ((s0  >= 0.f) ? s0  : 0.01f*s0)  * w2tail.x;
                p      += ((s1v >= 0.f) ? s1v : 0.01f*s1v) * w2tail.y;
                p      += ((s2  >= 0.f) ? s2  : 0.01f*s2)  * w2tail.z;
                p      += ((s3  >= 0.f) ? s3  : 0.01f*s3)  * w2tail.w;
                partB[r] = p;
            }
        }

        // =================== Stages D/E/F fused per 4-row half ==============
        float w2head = sWs2[lane];
        #pragma unroll
        for (int p = 0; p < 2; p++) {
            // ---- D: out_vec ----
            u64 oxy[4] = {0ull,0ull,0ull,0ull};
            float ozv[4] = {0.f,0.f,0.f,0.f};
            #pragma unroll
            for (int t = 0; t < 2; t++) {
                __syncwarp();
                if ((lane >> 4) == t) {
                    int h0 = 2*lane - 32*t;
                    #pragma unroll
                    for (int r2 = 0; r2 < 4; r2++) {
                        *(u64*)(ws + r2*96 +  0 + h0) = pax[p*4+r2];
                        *(u64*)(ws + r2*96 + 32 + h0) = pay[p*4+r2];
                        *(u64*)(ws + r2*96 + 64 + h0) = paz[p*4+r2];
                    }
                }
                __syncwarp();
                for (int hq = 0; hq < 8; hq++) {
                    float4 xv[4][3];
                    #pragma unroll
                    for (int r2 = 0; r2 < 4; r2++) {
                        xv[r2][0] = wsv4[r2*24 + 0*8 + hq];
                        xv[r2][1] = wsv4[r2*24 + 1*8 + hq];
                        xv[r2][2] = wsv4[r2*24 + 2*8 + hq];
                    }
                    float4 w4 = sWv21_f4[(t*8 + hq)*32 + lane];
                    #pragma unroll
                    for (int e = 0; e < 4; e++) {
                        float w = fcomp(w4, e);
                        u64 ww = pk2(w, w);
                        #pragma unroll
                        for (int r2 = 0; r2 < 4; r2++) {
                            fma2(oxy[r2], pk2(fcomp(xv[r2][0],e), fcomp(xv[r2][1],e)), ww);
                            ozv[r2] += w * fcomp(xv[r2][2], e);
                        }
                    }
                }
            }
            float v2x[4], v2y[4], v2z[4];
            #pragma unroll
            for (int r2 = 0; r2 < 4; r2++) {
                float ox, oy; upk2(ox, oy, oxy[r2]);
                float g = gg[p*4+r2];
                v2x[r2] = g*ox; v2y[r2] = g*oy; v2z[r2] = g*ozv[r2];
            }

            // ---- E: VNLeakyReLU ----
            __syncwarp();
            #pragma unroll
            for (int r2 = 0; r2 < 4; r2++) {
                ws[r2*96 +  0 + lane] = v2x[r2];
                ws[r2*96 + 32 + lane] = v2y[r2];
                ws[r2*96 + 64 + lane] = v2z[r2];
            }
            __syncwarp();
            u64 dxy[4] = {0ull,0ull,0ull,0ull};
            float dzv[4] = {0.f,0.f,0.f,0.f};
            for (int cq = 0; cq < 8; cq++) {
                float4 xv[4][3];
                #pragma unroll
                for (int r2 = 0; r2 < 4; r2++) {
                    xv[r2][0] = wsv4[r2*24 + 0*8 + cq];
                    xv[r2][1] = wsv4[r2*24 + 1*8 + cq];
                    xv[r2][2] = wsv4[r2*24 + 2*8 + cq];
                }
                float4 w4 = sWd1_f4[cq*32 + lane];
                #pragma unroll
                for (int e = 0; e < 4; e++) {
                    float w = fcomp(w4, e);
                    u64 ww = pk2(w, w);
                    #pragma unroll
                    for (int r2 = 0; r2 < 4; r2++) {
                        fma2(dxy[r2], pk2(fcomp(xv[r2][0],e), fcomp(xv[r2][1],e)), ww);
                        dzv[r2] += w * fcomp(xv[r2][2], e);
                    }
                }
            }
            float v3x[4], v3y[4], v3z[4];
            #pragma unroll
            for (int r2 = 0; r2 < 4; r2++) {
                float dx, dy; upk2(dx, dy, dxy[r2]);
                float dz = dzv[r2];
                float dot = v2x[r2]*dx + v2y[r2]*dy + v2z[r2]*dz;
                float dsq = dx*dx + dy*dy + dz*dz;
                float tt  = dot / (dsq + 1e-6f);
                float rx = (dot >= 0.f) ? v2x[r2] : (v2x[r2] - tt*dx);
                float ry = (dot >= 0.f) ? v2y[r2] : (v2y[r2] - tt*dy);
                float rz = (dot >= 0.f) ? v2z[r2] : (v2z[r2] - tt*dz);
                v3x[r2] = 0.2f*v2x[r2] + 0.8f*rx;
                v3y[r2] = 0.2f*v2y[r2] + 0.8f*ry;
                v3z[r2] = 0.2f*v2z[r2] + 0.8f*rz;
            }

            // ---- F: layer 2 + output ----
            __syncwarp();
            #pragma unroll
            for (int r2 = 0; r2 < 4; r2++) {
                ws[r2*96 +  0 + lane] = v3x[r2];
                ws[r2*96 + 32 + lane] = v3y[r2];
                ws[r2*96 + 64 + lane] = v3z[r2];
            }
            __syncwarp();
            u64 bxy[4] = {0ull,0ull,0ull,0ull};
            float bzv[4] = {0.f,0.f,0.f,0.f};
            for (int cq = 0; cq < 8; cq++) {
                float4 xv[4][3];
                #pragma unroll
                for (int r2 = 0; r2 < 4; r2++) {
                    xv[r2][0] = wsv4[r2*24 + 0*8 + cq];
                    xv[r2][1] = wsv4[r2*24 + 1*8 + cq];
                    xv[r2][2] = wsv4[r2*24 + 2*8 + cq];
                }
                float4 w4 = sWv12_f4[cq*32 + lane];
                #pragma unroll
                for (int e = 0; e < 4; e++) {
                    float w = fcomp(w4, e);
                    u64 ww = pk2(w, w);
                    #pragma unroll
                    for (int r2 = 0; r2 < 4; r2++) {
                        fma2(bxy[r2], pk2(fcomp(xv[r2][0],e), fcomp(xv[r2][1],e)), ww);
                        bzv[r2] += w * fcomp(xv[r2][2], e);
                    }
                }
            }
            float res[4];
            #pragma unroll
            for (int r2 = 0; r2 < 4; r2++) {
                float bx, by; upk2(bx, by, bxy[r2]);
                float bz = bzv[r2];
                float vn2 = sqrtf(bx*bx + by*by + bz*bz);
                float pp = vn2 * w2head + partB[p*4+r2];
                #pragma unroll
                for (int off = 16; off > 0; off >>= 1)
                    pp += __shfl_xor_sync(FULLMASK, pp, off);
                res[r2] = pp;
            }
            if (lane == 0) {
                int mb = base + p*4;
                if (mb + 3 < M) {
                    *(float4*)(out + mb) = make_float4(res[0], res[1], res[2], res[3]);
                } else {
                    #pragma unroll
                    for (int r2 = 0; r2 < 4; r2++)
                        if (mb + r2 < M) out[mb + r2] = res[r2];
                }
            }
        }
        __syncwarp();
    }
}

extern "C" void kernel_launch(void* const* d_in, const int* in_sizes, int n_in,
                              void* d_out, int out_size)
{
    const float* g_sca  = (const float*)d_in[0];
    const float* g_vec  = (const float*)d_in[1];
    const int*   g_idx  = (const int*)  d_in[2];
    const float* gWv11  = (const float*)d_in[3];
    const float* gWv21  = (const float*)d_in[4];
    const float* gWs1   = (const float*)d_in[5];
    const float* gWg1   = (const float*)d_in[6];
    const float* gbg1   = (const float*)d_in[7];
    const float* gWd1   = (const float*)d_in[8];
    const float* gWv12  = (const float*)d_in[9];
    const float* gWs2   = (const float*)d_in[11];
    float* out = (float*)d_out;
    const int M = in_sizes[2];

    const int smem_bytes = SMEM_FLOATS * (int)sizeof(float);  // 232192 B
    cudaFuncSetAttribute(frontier_vn_kernel,
                         cudaFuncAttributeMaxDynamicSharedMemorySize, smem_bytes);

    int sms = 148;
    cudaDeviceGetAttribute(&sms, cudaDevAttrMultiProcessorCount, 0);

    frontier_vn_kernel<<<sms, THREADS, smem_bytes>>>(
        g_sca, g_vec, g_idx,
        gWv11, gWv21, gWs1, gWg1, gbg1, gWd1, gWv12, gWs2,
        out, M);
}